// round 12
// baseline (speedup 1.0000x reference)
#include <cuda_runtime.h>
#include <math.h>

// Problem dims (fixed)
#define T_DIM 4
#define B_DIM 16
#define N_TOK 256
#define C_DIM 512
#define HID_DIM 2048
#define H_HEADS 8
#define HD 64
#define M_ROWS (T_DIM * B_DIM * N_TOK)   // 16384 rows for all GEMMs
#define RN (B_DIM * N_TOK)               // 4096 (b,n) pairs per timestep
#define NTILE 128                        // 16384 = 128 tiles x 128 rows

// ---------------------------------------------------------------------------
// Scratch (device globals; no runtime allocation allowed)
// ---------------------------------------------------------------------------
__device__ float  g_scratch[(size_t)M_ROWS * HID_DIM]; // 128 MB: GEMM pre-activations
__device__ float  g_qs[(size_t)M_ROWS * C_DIM];        // q spikes (reused for p spikes)
__device__ float  g_ks[(size_t)M_ROWS * C_DIM];        // k spikes
__device__ float  g_vs[(size_t)M_ROWS * C_DIM];        // v spikes (reused for f2 out)
__device__ float  g_ob[(size_t)M_ROWS * C_DIM];        // attention out -> o spikes
__device__ float  g_x1[(size_t)M_ROWS * C_DIM];        // residual x + proj
__device__ float  g_part[NTILE * HID_DIM];             // stage-1 partials P[128,C]
__device__ float  g_mean[HID_DIM];
__device__ float  g_rs[HID_DIM];

// ---------------------------------------------------------------------------
// SGEMM: Y[M,N] = A[M,K] @ W[K,N] + bias  (fp32, 128x128x16, 8x8/thread)
// Single accumulator per output, ascending-k FFMA chain, bias added last.
// (FROZEN: best-matching GEMM structure across R1-R11.)
// ---------------------------------------------------------------------------
__global__ void __launch_bounds__(256)
sgemm_bias(const float* __restrict__ A, const float* __restrict__ W,
           const float* __restrict__ bias, float* __restrict__ Y,
           int M, int N, int K)
{
    const int BM = 128, BN = 128, BK = 16, TM = 8, TN = 8;
    __shared__ __align__(16) float As[BK][BM];
    __shared__ __align__(16) float Bs[BK][BN];

    const int tid  = threadIdx.x;
    const int trow = (tid / 16) * TM;   // 0..120
    const int tcol = (tid % 16) * TN;   // 0..120

    const float* Ab = A + (size_t)blockIdx.y * BM * K;
    const float* Wb = W + (size_t)blockIdx.x * BN;

    float acc[TM][TN];
#pragma unroll
    for (int i = 0; i < TM; i++)
#pragma unroll
        for (int j = 0; j < TN; j++) acc[i][j] = 0.f;

    for (int k0 = 0; k0 < K; k0 += BK) {
        // Load A tile (BM x BK), store transposed As[k][m]
#pragma unroll
        for (int i = 0; i < (BM * BK) / 256; i++) {
            int idx = tid + i * 256;
            int r = idx / BK, c = idx % BK;
            As[c][r] = Ab[(size_t)r * K + k0 + c];
        }
        // Load W tile (BK x BN)
#pragma unroll
        for (int i = 0; i < (BK * BN) / 256; i++) {
            int idx = tid + i * 256;
            int r = idx / BN, c = idx % BN;
            Bs[r][c] = Wb[(size_t)(k0 + r) * N + c];
        }
        __syncthreads();

#pragma unroll
        for (int k = 0; k < BK; k++) {
            float4 a0 = *reinterpret_cast<const float4*>(&As[k][trow]);
            float4 a1 = *reinterpret_cast<const float4*>(&As[k][trow + 4]);
            float4 b0 = *reinterpret_cast<const float4*>(&Bs[k][tcol]);
            float4 b1 = *reinterpret_cast<const float4*>(&Bs[k][tcol + 4]);
            float a[8] = {a0.x, a0.y, a0.z, a0.w, a1.x, a1.y, a1.z, a1.w};
            float b[8] = {b0.x, b0.y, b0.z, b0.w, b1.x, b1.y, b1.z, b1.w};
#pragma unroll
            for (int i = 0; i < TM; i++)
#pragma unroll
                for (int j = 0; j < TN; j++)
                    acc[i][j] = __fmaf_rn(a[i], b[j], acc[i][j]);
        }
        __syncthreads();
    }

#pragma unroll
    for (int i = 0; i < TM; i++) {
        size_t row = (size_t)blockIdx.y * BM + trow + i;
#pragma unroll
        for (int j = 0; j < TN; j++) {
            int col = blockIdx.x * BN + tcol + j;
            Y[row * N + col] = __fadd_rn(acc[i][j], bias[col]);
        }
    }
}

// ---------------------------------------------------------------------------
// BN stats: faithful XLA GPU two-kernel split reduction.
//   Split: (16384, C) -> (128 tiles x 128 rows, C).
//   Stage 1 (per tile): thread (x=col, y) sums rows {ty, ty+32, ty+64, ty+96}
//     in order (fp32); smem transpose; shfl_down tree (16,8,4,2,1);
//     lane0 writes tile partial P[tile][col].
//   Stage 2: same structure over the 128 partials per column:
//     thread y sums P[ty], P[ty+32], P[ty+64], P[ty+96]; transpose; tree;
//     result * 2^-14 (exact).
//   Var pass: identical two-stage over separately-rounded fp32 (x-mean)^2.
//   rs = rsqrtf(var + 1e-5f)  [library rsqrtf — frozen best].
// mode: 0 = sum(Y), 1 = sum((Y-mean)^2)
// ---------------------------------------------------------------------------
__global__ void __launch_bounds__(1024)
bn_stage1(const float* __restrict__ Y, float* __restrict__ P, int C, int mode)
{
    __shared__ float sm[32][33];
    const int c0   = blockIdx.x * 32;
    const int tile = blockIdx.y;
    const int tx = threadIdx.x;
    const int ty = threadIdx.y;
    const float m = (mode == 1) ? g_mean[c0 + tx] : 0.f;

    float acc = 0.f;
#pragma unroll
    for (int i = 0; i < 4; i++) {
        int r = tile * 128 + ty + i * 32;
        float v = Y[(size_t)r * C + c0 + tx];
        if (mode == 1) {
            float d = __fsub_rn(v, m);
            v = __fmul_rn(d, d);          // separate fp32 rounding (no FMA)
        }
        acc = __fadd_rn(acc, v);
    }
    sm[ty][tx] = acc;
    __syncthreads();
    // warp ty reduces channel c0+ty: partials sm[0..31][ty]
    float v = sm[tx][ty];
#pragma unroll
    for (int off = 16; off; off >>= 1)
        v = __fadd_rn(v, __shfl_down_sync(0xffffffffu, v, off));
    if (tx == 0)
        P[(size_t)tile * C + c0 + ty] = v;
}

__global__ void __launch_bounds__(1024)
bn_stage2(const float* __restrict__ P, int C, int mode)
{
    __shared__ float sm[32][33];
    const int c0 = blockIdx.x * 32;
    const int tx = threadIdx.x;
    const int ty = threadIdx.y;

    float acc = 0.f;
#pragma unroll
    for (int i = 0; i < 4; i++) {
        int r = ty + i * 32;              // 128 partials, 4-strided in order
        acc = __fadd_rn(acc, P[(size_t)r * C + c0 + tx]);
    }
    sm[ty][tx] = acc;
    __syncthreads();
    float v = sm[tx][ty];
#pragma unroll
    for (int off = 16; off; off >>= 1)
        v = __fadd_rn(v, __shfl_down_sync(0xffffffffu, v, off));
    if (tx == 0) {
        float red = __fmul_rn(v, 6.103515625e-05f);   // /16384, exact
        if (mode == 0) {
            g_mean[c0 + ty] = red;
        } else {
            float arg = __fadd_rn(red, 1e-5f);
            g_rs[c0 + ty] = rsqrtf(arg);              // libdevice path (frozen)
        }
    }
}

// ---------------------------------------------------------------------------
// LIF over T=4, BN applied in the reference's fp32 op order:
//   pre = (((h - mean) * rs) * gamma) + beta
//   mem = mem + (pre - mem) * 0.5 ; spk = (mem - 1 > 0) ; detach-reset
// ---------------------------------------------------------------------------
__global__ void lif_kernel(const float* __restrict__ Y, float* __restrict__ OUT,
                           const float* __restrict__ gamma,
                           const float* __restrict__ beta,
                           int Cout, int use_bn)
{
    int idx = blockIdx.x * blockDim.x + threadIdx.x;
    int total = RN * Cout;
    if (idx >= total) return;
    int c = idx & (Cout - 1);   // Cout is a power of two
    float mean = 0.f, rs = 1.f, ga = 1.f, be = 0.f;
    if (use_bn) {
        mean = g_mean[c]; rs = g_rs[c]; ga = gamma[c]; be = beta[c];
    }
    size_t stride = (size_t)RN * Cout;

    float mem = 0.f;
#pragma unroll
    for (int t = 0; t < T_DIM; t++) {
        float h = Y[(size_t)t * stride + idx];
        float pre;
        if (use_bn) {
            float n1 = __fmul_rn(__fsub_rn(h, mean), rs);
            pre = __fmaf_rn(n1, ga, be);
        } else {
            pre = h;
        }
        mem = __fmaf_rn(__fsub_rn(pre, mem), 0.5f, mem);   // TAU=2
        float d = __fsub_rn(mem, 1.0f);
        float spk = (d > 0.f) ? 1.0f : 0.0f;
        if (spk > 0.f) mem = 0.f;          // detach-reset
        OUT[(size_t)t * stride + idx] = spk;
    }
}

// ---------------------------------------------------------------------------
// Spiking self-attention, softmax-free. (q k^T) v == q (k^T v): binary spikes
// make both orders exact integer arithmetic in fp32 -> bit-identical to ref.
// One block per (t*b, h).
// ---------------------------------------------------------------------------
__global__ void __launch_bounds__(256)
attn_kernel(const float* __restrict__ Q, const float* __restrict__ K,
            const float* __restrict__ V, float* __restrict__ O)
{
    const int h  = blockIdx.x;
    const int tb = blockIdx.y;
    const size_t base = (size_t)tb * N_TOK * C_DIM + (size_t)h * HD;

    __shared__ float KV[64 * 64];
    __shared__ float pool[64 * 65]; // phase1: Ks[0..2047], Vs[2048..4095]; phase2: Qs
    float* Ks = pool;
    float* Vs = pool + 2048;

    const int tid = threadIdx.x;

    // ---- Phase 1: KV[d1][d2] = sum_n K[n,d1] * V[n,d2]  (64x64)
    float acc[16];
#pragma unroll
    for (int j = 0; j < 16; j++) acc[j] = 0.f;
    const int d1  = tid >> 2;
    const int d2b = (tid & 3) * 16;

    for (int n0 = 0; n0 < N_TOK; n0 += 32) {
#pragma unroll
        for (int i = tid; i < 32 * 64; i += 256) {
            int r = i >> 6, d = i & 63;
            size_t g = base + (size_t)(n0 + r) * C_DIM + d;
            Ks[i] = K[g];
            Vs[i] = V[g];
        }
        __syncthreads();
#pragma unroll
        for (int n = 0; n < 32; n++) {
            float a = Ks[n * 64 + d1];
#pragma unroll
            for (int j = 0; j < 16; j++)
                acc[j] += a * Vs[n * 64 + d2b + j];
        }
        __syncthreads();
    }
#pragma unroll
    for (int j = 0; j < 16; j++)
        KV[d1 * 64 + d2b + j] = acc[j];
    __syncthreads();

    // ---- Phase 2: O = 0.125 * Q @ KV (256x64), 64-row blocks, 4x4 microtiles
    const int trow = (tid >> 4) * 4;
    const int tcol = (tid & 15) * 4;
    float* Qs = pool;  // 64 x 65 (padded)

    for (int rb = 0; rb < 4; rb++) {
#pragma unroll
        for (int i = tid; i < 64 * 64; i += 256) {
            int r = i >> 6, d = i & 63;
            Qs[r * 65 + d] = Q[base + (size_t)(rb * 64 + r) * C_DIM + d];
        }
        __syncthreads();

        float o[4][4];
#pragma unroll
        for (int i = 0; i < 4; i++)
#pragma unroll
            for (int j = 0; j < 4; j++) o[i][j] = 0.f;

#pragma unroll
        for (int k = 0; k < 64; k++) {
            float a[4], b[4];
#pragma unroll
            for (int i = 0; i < 4; i++) a[i] = Qs[(trow + i) * 65 + k];
#pragma unroll
            for (int j = 0; j < 4; j++) b[j] = KV[k * 64 + tcol + j];
#pragma unroll
            for (int i = 0; i < 4; i++)
#pragma unroll
                for (int j = 0; j < 4; j++)
                    o[i][j] += a[i] * b[j];
        }
#pragma unroll
        for (int i = 0; i < 4; i++)
#pragma unroll
            for (int j = 0; j < 4; j++)
                O[base + (size_t)(rb * 64 + trow + i) * C_DIM + tcol + j] = 0.125f * o[i][j];
        __syncthreads();
    }
}

// ---------------------------------------------------------------------------
// Elementwise residual add
// ---------------------------------------------------------------------------
__global__ void add_kernel(const float* __restrict__ a, const float* __restrict__ b,
                           float* __restrict__ o, int n)
{
    int i = blockIdx.x * blockDim.x + threadIdx.x;
    if (i < n) o[i] = __fadd_rn(a[i], b[i]);
}

// ---------------------------------------------------------------------------
// Launcher
// ---------------------------------------------------------------------------
static float* s_part = 0;

static void stage_lin_bn_lif(const float* A, const float* W, const float* b,
                             const float* g, const float* be,
                             float* Y, float* OUT, int N, int K)
{
    dim3 grid(N / 128, M_ROWS / 128);
    sgemm_bias<<<grid, 256>>>(A, W, b, Y, M_ROWS, N, K);
    dim3 sblk(32, 32);
    dim3 s1grid(N / 32, NTILE);
    // mean: two-stage reduce of Y
    bn_stage1<<<s1grid, sblk>>>(Y, s_part, N, 0);
    bn_stage2<<<N / 32, sblk>>>(s_part, N, 0);
    // var: two-stage reduce of (Y - mean)^2
    bn_stage1<<<s1grid, sblk>>>(Y, s_part, N, 1);
    bn_stage2<<<N / 32, sblk>>>(s_part, N, 1);
    int total = RN * N;
    lif_kernel<<<(total + 255) / 256, 256>>>(Y, OUT, g, be, N, 1);
}

extern "C" void kernel_launch(void* const* d_in, const int* in_sizes, int n_in,
                              void* d_out, int out_size)
{
    const float* x    = (const float*)d_in[0];
    const float* qW   = (const float*)d_in[1];
    const float* qb   = (const float*)d_in[2];
    const float* qg   = (const float*)d_in[3];
    const float* qbe  = (const float*)d_in[4];
    const float* kW   = (const float*)d_in[5];
    const float* kb   = (const float*)d_in[6];
    const float* kg   = (const float*)d_in[7];
    const float* kbe  = (const float*)d_in[8];
    const float* vW   = (const float*)d_in[9];
    const float* vb   = (const float*)d_in[10];
    const float* vg   = (const float*)d_in[11];
    const float* vbe  = (const float*)d_in[12];
    const float* pW   = (const float*)d_in[13];
    const float* pb   = (const float*)d_in[14];
    const float* pg   = (const float*)d_in[15];
    const float* pbe  = (const float*)d_in[16];
    const float* f1W  = (const float*)d_in[17];
    const float* f1b  = (const float*)d_in[18];
    const float* f1g  = (const float*)d_in[19];
    const float* f1be = (const float*)d_in[20];
    const float* f2W  = (const float*)d_in[21];
    const float* f2b  = (const float*)d_in[22];
    const float* f2g  = (const float*)d_in[23];
    const float* f2be = (const float*)d_in[24];
    float* out = (float*)d_out;

    float *scratch, *qs, *ks, *vs, *ob, *x1;
    cudaGetSymbolAddress((void**)&scratch, g_scratch);
    cudaGetSymbolAddress((void**)&qs, g_qs);
    cudaGetSymbolAddress((void**)&ks, g_ks);
    cudaGetSymbolAddress((void**)&vs, g_vs);
    cudaGetSymbolAddress((void**)&ob, g_ob);
    cudaGetSymbolAddress((void**)&x1, g_x1);
    cudaGetSymbolAddress((void**)&s_part, g_part);

    const int NC = M_ROWS * C_DIM;  // 8,388,608

    // --- SSA: q, k, v projections (linear + BN + LIF) ---
    stage_lin_bn_lif(x, qW, qb, qg, qbe, scratch, qs, C_DIM, C_DIM);
    stage_lin_bn_lif(x, kW, kb, kg, kbe, scratch, ks, C_DIM, C_DIM);
    stage_lin_bn_lif(x, vW, vb, vg, vbe, scratch, vs, C_DIM, C_DIM);

    // --- attention: o = SCALE * q @ (k^T v), exact for binary spikes ---
    attn_kernel<<<dim3(H_HEADS, T_DIM * B_DIM), 256>>>(qs, ks, vs, ob);

    // --- LIF on attention output (no BN; exact dyadic arithmetic) ---
    lif_kernel<<<(RN * C_DIM + 255) / 256, 256>>>(ob, ob, (const float*)0,
                                                  (const float*)0, C_DIM, 0);

    // --- projection p (linear + BN + LIF), spikes into qs (reuse) ---
    stage_lin_bn_lif(ob, pW, pb, pg, pbe, scratch, qs, C_DIM, C_DIM);

    // --- residual: x1 = x + o_proj_spikes ---
    add_kernel<<<(NC + 255) / 256, 256>>>(x, qs, x1, NC);

    // --- MLP: f1 (512->2048), LIF in-place in scratch ---
    stage_lin_bn_lif(x1, f1W, f1b, f1g, f1be, scratch, scratch, HID_DIM, C_DIM);

    // --- MLP: f2 (2048->512), output into vs (reuse), LIF in-place ---
    stage_lin_bn_lif(scratch, f2W, f2b, f2g, f2be, vs, vs, C_DIM, HID_DIM);

    // --- final residual ---
    add_kernel<<<(NC + 255) / 256, 256>>>(x1, vs, out, NC);
}

// round 13
// speedup vs baseline: 1.2017x; 1.2017x over previous
#include <cuda_runtime.h>
#include <math.h>

// Problem dims (fixed)
#define T_DIM 4
#define B_DIM 16
#define N_TOK 256
#define C_DIM 512
#define HID_DIM 2048
#define H_HEADS 8
#define HD 64
#define M_ROWS (T_DIM * B_DIM * N_TOK)   // 16384
#define RN (B_DIM * N_TOK)               // 4096
#define NTILE 128                        // 16384 = 128 tiles x 128 rows
#define NC (M_ROWS * C_DIM)              // 8,388,608

// ---------------------------------------------------------------------------
// Scratch (device globals; no runtime allocation allowed)
// ---------------------------------------------------------------------------
__device__ float  g_scratch[(size_t)M_ROWS * HID_DIM]; // GEMM pre-activations (fits 3x qkv slices)
__device__ float  g_qs[(size_t)M_ROWS * C_DIM];
__device__ float  g_ks[(size_t)M_ROWS * C_DIM];
__device__ float  g_vs[(size_t)M_ROWS * C_DIM];
__device__ float  g_ob[(size_t)M_ROWS * C_DIM];
__device__ float  g_x1[(size_t)M_ROWS * C_DIM];
__device__ float  g_part[3 * NTILE * C_DIM > NTILE * HID_DIM ? 3 * NTILE * C_DIM : NTILE * HID_DIM];
__device__ float  g_mean[3 * C_DIM > HID_DIM ? 3 * C_DIM : HID_DIM];
__device__ float  g_rs[3 * C_DIM > HID_DIM ? 3 * C_DIM : HID_DIM];

// ---------------------------------------------------------------------------
// SGEMM: Y[M,N] = A[M,K] @ W[K,N] + bias.  Double-buffered smem, 128x128x16,
// 8x8/thread, 256 threads. Per-output accumulation is a single fp32 FFMA
// chain over ascending k with bias added last — BIT-IDENTICAL to R12.
// grid.z selects (W,b) and output slice: merges the q/k/v GEMMs.
// ---------------------------------------------------------------------------
__global__ void __launch_bounds__(256)
sgemm_bias(const float* __restrict__ A,
           const float* __restrict__ W0, const float* __restrict__ W1,
           const float* __restrict__ W2,
           const float* __restrict__ b0, const float* __restrict__ b1,
           const float* __restrict__ b2,
           float* __restrict__ Y, int M, int N, int K, int ysl)
{
    const int BM = 128, BN = 128, BK = 16, TM = 8, TN = 8;
    __shared__ __align__(16) float As[2][BK][BM];
    __shared__ __align__(16) float Bs[2][BK][BN];

    const int tid = threadIdx.x;
    const int z   = blockIdx.z;
    const float* W    = (z == 0) ? W0 : (z == 1 ? W1 : W2);
    const float* bias = (z == 0) ? b0 : (z == 1 ? b1 : b2);
    float* Yz = Y + (size_t)z * ysl;

    const int trow = (tid / 16) * TM;
    const int tcol = (tid % 16) * TN;
    const float* Ab = A + (size_t)blockIdx.y * BM * K;
    const float* Wb = W + (size_t)blockIdx.x * BN;

    float4 ra[2], rb[2];

#define LOAD_TILE(kt)                                                        \
    {                                                                        \
        _Pragma("unroll")                                                    \
        for (int i = 0; i < 2; i++) {                                        \
            int idx4 = tid + 256 * i;                                        \
            int r  = idx4 >> 2, c4 = (idx4 & 3) * 4;                         \
            ra[i] = *reinterpret_cast<const float4*>(                        \
                &Ab[(size_t)r * K + (kt) * BK + c4]);                        \
            int r2 = idx4 >> 5, c42 = (idx4 & 31) * 4;                       \
            rb[i] = *reinterpret_cast<const float4*>(                        \
                &Wb[(size_t)((kt) * BK + r2) * N + c42]);                    \
        }                                                                    \
    }

#define STORE_TILE(buf)                                                      \
    {                                                                        \
        _Pragma("unroll")                                                    \
        for (int i = 0; i < 2; i++) {                                        \
            int idx4 = tid + 256 * i;                                        \
            int r  = idx4 >> 2, c4 = (idx4 & 3) * 4;                         \
            As[buf][c4 + 0][r] = ra[i].x;                                    \
            As[buf][c4 + 1][r] = ra[i].y;                                    \
            As[buf][c4 + 2][r] = ra[i].z;                                    \
            As[buf][c4 + 3][r] = ra[i].w;                                    \
            int r2 = idx4 >> 5, c42 = (idx4 & 31) * 4;                       \
            *reinterpret_cast<float4*>(&Bs[buf][r2][c42]) = rb[i];           \
        }                                                                    \
    }

    float acc[TM][TN];
#pragma unroll
    for (int i = 0; i < TM; i++)
#pragma unroll
        for (int j = 0; j < TN; j++) acc[i][j] = 0.f;

    LOAD_TILE(0);
    STORE_TILE(0);
    __syncthreads();

    const int nt = K / BK;
    for (int t = 0; t < nt; t++) {
        const int cur = t & 1;
        if (t + 1 < nt) LOAD_TILE(t + 1);

#pragma unroll
        for (int k = 0; k < BK; k++) {
            float4 a0 = *reinterpret_cast<const float4*>(&As[cur][k][trow]);
            float4 a1 = *reinterpret_cast<const float4*>(&As[cur][k][trow + 4]);
            float4 b0v = *reinterpret_cast<const float4*>(&Bs[cur][k][tcol]);
            float4 b1v = *reinterpret_cast<const float4*>(&Bs[cur][k][tcol + 4]);
            float a[8] = {a0.x, a0.y, a0.z, a0.w, a1.x, a1.y, a1.z, a1.w};
            float b[8] = {b0v.x, b0v.y, b0v.z, b0v.w, b1v.x, b1v.y, b1v.z, b1v.w};
#pragma unroll
            for (int i = 0; i < TM; i++)
#pragma unroll
                for (int j = 0; j < TN; j++)
                    acc[i][j] = __fmaf_rn(a[i], b[j], acc[i][j]);
        }

        if (t + 1 < nt) {
            STORE_TILE(cur ^ 1);
            __syncthreads();
        }
    }

#pragma unroll
    for (int i = 0; i < TM; i++) {
        size_t row = (size_t)blockIdx.y * BM + trow + i;
#pragma unroll
        for (int j = 0; j < TN; j++) {
            int col = blockIdx.x * BN + tcol + j;
            Yz[row * N + col] = __fadd_rn(acc[i][j], bias[col]);
        }
    }
#undef LOAD_TILE
#undef STORE_TILE
}

// ---------------------------------------------------------------------------
// BN stats: XLA GPU two-kernel split reduction (FROZEN numerics from R12).
// grid.z batches independent tensors (q/k/v); ysl = Y slice stride.
// ---------------------------------------------------------------------------
__global__ void __launch_bounds__(1024)
bn_stage1(const float* __restrict__ Y, float* __restrict__ P, int C, int mode,
          int ysl)
{
    __shared__ float sm[32][33];
    const int z    = blockIdx.z;
    const int c0   = blockIdx.x * 32;
    const int tile = blockIdx.y;
    const int tx = threadIdx.x;
    const int ty = threadIdx.y;
    const float* Yz = Y + (size_t)z * ysl;
    float* Pz = P + (size_t)z * NTILE * C;
    const float m = (mode == 1) ? g_mean[z * C + c0 + tx] : 0.f;

    float acc = 0.f;
#pragma unroll
    for (int i = 0; i < 4; i++) {
        int r = tile * 128 + ty + i * 32;
        float v = Yz[(size_t)r * C + c0 + tx];
        if (mode == 1) {
            float d = __fsub_rn(v, m);
            v = __fmul_rn(d, d);          // separate fp32 rounding (no FMA)
        }
        acc = __fadd_rn(acc, v);
    }
    sm[ty][tx] = acc;
    __syncthreads();
    float v = sm[tx][ty];
#pragma unroll
    for (int off = 16; off; off >>= 1)
        v = __fadd_rn(v, __shfl_down_sync(0xffffffffu, v, off));
    if (tx == 0)
        Pz[(size_t)tile * C + c0 + ty] = v;
}

__global__ void __launch_bounds__(1024)
bn_stage2(const float* __restrict__ P, int C, int mode)
{
    __shared__ float sm[32][33];
    const int z  = blockIdx.z;
    const int c0 = blockIdx.x * 32;
    const int tx = threadIdx.x;
    const int ty = threadIdx.y;
    const float* Pz = P + (size_t)z * NTILE * C;

    float acc = 0.f;
#pragma unroll
    for (int i = 0; i < 4; i++) {
        int r = ty + i * 32;
        acc = __fadd_rn(acc, Pz[(size_t)r * C + c0 + tx]);
    }
    sm[ty][tx] = acc;
    __syncthreads();
    float v = sm[tx][ty];
#pragma unroll
    for (int off = 16; off; off >>= 1)
        v = __fadd_rn(v, __shfl_down_sync(0xffffffffu, v, off));
    if (tx == 0) {
        float red = __fmul_rn(v, 6.103515625e-05f);   // /16384, exact
        if (mode == 0) {
            g_mean[z * C + c0 + ty] = red;
        } else {
            float arg = __fadd_rn(red, 1e-5f);
            g_rs[z * C + c0 + ty] = rsqrtf(arg);      // libdevice path (FROZEN)
        }
    }
}

// ---------------------------------------------------------------------------
// LIF over T=4 (FROZEN numerics). Optional fused residual add:
// if RES != 0, writes fadd(RES[g], spk) instead of spk (same op/order as the
// standalone add kernel it replaces).
// ---------------------------------------------------------------------------
__global__ void lif_kernel(const float* __restrict__ Y, float* __restrict__ OUT,
                           const float* __restrict__ RES,
                           const float* __restrict__ gamma,
                           const float* __restrict__ beta,
                           int Cout, int use_bn, int soff)
{
    int idx = blockIdx.x * blockDim.x + threadIdx.x;
    int total = RN * Cout;
    if (idx >= total) return;
    int c = idx & (Cout - 1);
    float mean = 0.f, rs = 1.f, ga = 1.f, be = 0.f;
    if (use_bn) {
        mean = g_mean[soff + c]; rs = g_rs[soff + c];
        ga = gamma[c]; be = beta[c];
    }
    size_t stride = (size_t)RN * Cout;

    float mem = 0.f;
#pragma unroll
    for (int t = 0; t < T_DIM; t++) {
        size_t g = (size_t)t * stride + idx;
        float h = Y[g];
        float pre;
        if (use_bn) {
            float n1 = __fmul_rn(__fsub_rn(h, mean), rs);
            pre = __fmaf_rn(n1, ga, be);
        } else {
            pre = h;
        }
        mem = __fmaf_rn(__fsub_rn(pre, mem), 0.5f, mem);   // TAU=2
        float d = __fsub_rn(mem, 1.0f);
        float spk = (d > 0.f) ? 1.0f : 0.0f;
        if (spk > 0.f) mem = 0.f;
        OUT[g] = RES ? __fadd_rn(RES[g], spk) : spk;
    }
}

// ---------------------------------------------------------------------------
// Spiking self-attention (exact integer arithmetic; FROZEN).
// ---------------------------------------------------------------------------
__global__ void __launch_bounds__(256)
attn_kernel(const float* __restrict__ Q, const float* __restrict__ K,
            const float* __restrict__ V, float* __restrict__ O)
{
    const int h  = blockIdx.x;
    const int tb = blockIdx.y;
    const size_t base = (size_t)tb * N_TOK * C_DIM + (size_t)h * HD;

    __shared__ float KV[64 * 64];
    __shared__ float pool[64 * 65];
    float* Ks = pool;
    float* Vs = pool + 2048;

    const int tid = threadIdx.x;

    float acc[16];
#pragma unroll
    for (int j = 0; j < 16; j++) acc[j] = 0.f;
    const int d1  = tid >> 2;
    const int d2b = (tid & 3) * 16;

    for (int n0 = 0; n0 < N_TOK; n0 += 32) {
#pragma unroll
        for (int i = tid; i < 32 * 64; i += 256) {
            int r = i >> 6, d = i & 63;
            size_t g = base + (size_t)(n0 + r) * C_DIM + d;
            Ks[i] = K[g];
            Vs[i] = V[g];
        }
        __syncthreads();
#pragma unroll
        for (int n = 0; n < 32; n++) {
            float a = Ks[n * 64 + d1];
#pragma unroll
            for (int j = 0; j < 16; j++)
                acc[j] += a * Vs[n * 64 + d2b + j];
        }
        __syncthreads();
    }
#pragma unroll
    for (int j = 0; j < 16; j++)
        KV[d1 * 64 + d2b + j] = acc[j];
    __syncthreads();

    const int trow = (tid >> 4) * 4;
    const int tcol = (tid & 15) * 4;
    float* Qs = pool;

    for (int rb = 0; rb < 4; rb++) {
#pragma unroll
        for (int i = tid; i < 64 * 64; i += 256) {
            int r = i >> 6, d = i & 63;
            Qs[r * 65 + d] = Q[base + (size_t)(rb * 64 + r) * C_DIM + d];
        }
        __syncthreads();

        float o[4][4];
#pragma unroll
        for (int i = 0; i < 4; i++)
#pragma unroll
            for (int j = 0; j < 4; j++) o[i][j] = 0.f;

#pragma unroll
        for (int k = 0; k < 64; k++) {
            float a[4], b[4];
#pragma unroll
            for (int i = 0; i < 4; i++) a[i] = Qs[(trow + i) * 65 + k];
#pragma unroll
            for (int j = 0; j < 4; j++) b[j] = KV[k * 64 + tcol + j];
#pragma unroll
            for (int i = 0; i < 4; i++)
#pragma unroll
                for (int j = 0; j < 4; j++)
                    o[i][j] += a[i] * b[j];
        }
#pragma unroll
        for (int i = 0; i < 4; i++)
#pragma unroll
            for (int j = 0; j < 4; j++)
                O[base + (size_t)(rb * 64 + trow + i) * C_DIM + tcol + j] = 0.125f * o[i][j];
        __syncthreads();
    }
}

// ---------------------------------------------------------------------------
// Launcher
// ---------------------------------------------------------------------------
static float* s_part = 0;

static void run_stats(const float* Y, int C, int zc, int ysl)
{
    dim3 sblk(32, 32);
    dim3 s1(C / 32, NTILE, zc);
    dim3 s2(C / 32, 1, zc);
    bn_stage1<<<s1, sblk>>>(Y, s_part, C, 0, ysl);
    bn_stage2<<<s2, sblk>>>(s_part, C, 0);
    bn_stage1<<<s1, sblk>>>(Y, s_part, C, 1, ysl);
    bn_stage2<<<s2, sblk>>>(s_part, C, 1);
}

extern "C" void kernel_launch(void* const* d_in, const int* in_sizes, int n_in,
                              void* d_out, int out_size)
{
    const float* x    = (const float*)d_in[0];
    const float* qW   = (const float*)d_in[1];
    const float* qb   = (const float*)d_in[2];
    const float* qg   = (const float*)d_in[3];
    const float* qbe  = (const float*)d_in[4];
    const float* kW   = (const float*)d_in[5];
    const float* kb   = (const float*)d_in[6];
    const float* kg   = (const float*)d_in[7];
    const float* kbe  = (const float*)d_in[8];
    const float* vW   = (const float*)d_in[9];
    const float* vb   = (const float*)d_in[10];
    const float* vg   = (const float*)d_in[11];
    const float* vbe  = (const float*)d_in[12];
    const float* pW   = (const float*)d_in[13];
    const float* pb   = (const float*)d_in[14];
    const float* pg   = (const float*)d_in[15];
    const float* pbe  = (const float*)d_in[16];
    const float* f1W  = (const float*)d_in[17];
    const float* f1b  = (const float*)d_in[18];
    const float* f1g  = (const float*)d_in[19];
    const float* f1be = (const float*)d_in[20];
    const float* f2W  = (const float*)d_in[21];
    const float* f2b  = (const float*)d_in[22];
    const float* f2g  = (const float*)d_in[23];
    const float* f2be = (const float*)d_in[24];
    float* out = (float*)d_out;

    float *scratch, *qs, *ks, *vs, *ob, *x1;
    cudaGetSymbolAddress((void**)&scratch, g_scratch);
    cudaGetSymbolAddress((void**)&qs, g_qs);
    cudaGetSymbolAddress((void**)&ks, g_ks);
    cudaGetSymbolAddress((void**)&vs, g_vs);
    cudaGetSymbolAddress((void**)&ob, g_ob);
    cudaGetSymbolAddress((void**)&x1, g_x1);
    cudaGetSymbolAddress((void**)&s_part, g_part);

    const int LIF_BLOCKS = (RN * C_DIM + 255) / 256;

    // --- SSA: q,k,v projections MERGED into one GEMM launch (grid.z=3) ---
    sgemm_bias<<<dim3(C_DIM / 128, M_ROWS / 128, 3), 256>>>(
        x, qW, kW, vW, qb, kb, vb, scratch, M_ROWS, C_DIM, C_DIM, NC);
    run_stats(scratch, C_DIM, 3, NC);
    lif_kernel<<<LIF_BLOCKS, 256>>>(scratch,          qs, (const float*)0, qg, qbe, C_DIM, 1, 0);
    lif_kernel<<<LIF_BLOCKS, 256>>>(scratch + (size_t)NC,     ks, (const float*)0, kg, kbe, C_DIM, 1, C_DIM);
    lif_kernel<<<LIF_BLOCKS, 256>>>(scratch + (size_t)2 * NC, vs, (const float*)0, vg, vbe, C_DIM, 1, 2 * C_DIM);

    // --- attention + its LIF (exact) ---
    attn_kernel<<<dim3(H_HEADS, T_DIM * B_DIM), 256>>>(qs, ks, vs, ob);
    lif_kernel<<<LIF_BLOCKS, 256>>>(ob, ob, (const float*)0,
                                    (const float*)0, (const float*)0, C_DIM, 0, 0);

    // --- projection p; LIF fused with residual: x1 = x + spk ---
    sgemm_bias<<<dim3(C_DIM / 128, M_ROWS / 128, 1), 256>>>(
        ob, pW, pW, pW, pb, pb, pb, scratch, M_ROWS, C_DIM, C_DIM, 0);
    run_stats(scratch, C_DIM, 1, 0);
    lif_kernel<<<LIF_BLOCKS, 256>>>(scratch, x1, x, pg, pbe, C_DIM, 1, 0);

    // --- MLP f1 (512->2048), LIF in-place ---
    sgemm_bias<<<dim3(HID_DIM / 128, M_ROWS / 128, 1), 256>>>(
        x1, f1W, f1W, f1W, f1b, f1b, f1b, scratch, M_ROWS, HID_DIM, C_DIM, 0);
    run_stats(scratch, HID_DIM, 1, 0);
    lif_kernel<<<(RN * HID_DIM + 255) / 256, 256>>>(
        scratch, scratch, (const float*)0, f1g, f1be, HID_DIM, 1, 0);

    // --- MLP f2 (2048->512); LIF fused with final residual: out = x1 + spk ---
    sgemm_bias<<<dim3(C_DIM / 128, M_ROWS / 128, 1), 256>>>(
        scratch, f2W, f2W, f2W, f2b, f2b, f2b, vs, M_ROWS, C_DIM, HID_DIM, 0);
    run_stats(vs, C_DIM, 1, 0);
    lif_kernel<<<LIF_BLOCKS, 256>>>(vs, out, x1, f2g, f2be, C_DIM, 1, 0);
}